// round 7
// baseline (speedup 1.0000x reference)
#include <cuda_runtime.h>

// NSLayer via identity (I - x x^T)^k x = x (I - x^T x)^k:
//   out = x @ T,  T = sum_k c_k Abar^k,  Abar = I - x^T x (symmetric).
// Symmetric triangular Horner (36-entry iterates), vectorized by packing
// TWO MATRICES per thread into the f32x2 lanes (thread t of a 64-thread
// block handles matrices t and t+64). Every op is the plain scalar
// algorithm on .f32x2 pairs: no broadcasts, no mirrors, no lane swaps.

#define NTHR 64
#define MPB  128          // matrices per block (2 per thread)
#define SROW 66           // floats per matrix region (64 + pad), even -> 8B aligned

typedef unsigned long long u64;

__device__ __forceinline__ u64 pack2(float a, float b) {
    u64 r; asm("mov.b64 %0, {%1, %2};" : "=l"(r) : "f"(a), "f"(b)); return r;
}
__device__ __forceinline__ void unpack2(u64 v, float &a, float &b) {
    asm("mov.b64 {%0, %1}, %2;" : "=f"(a), "=f"(b) : "l"(v));
}
__device__ __forceinline__ u64 fma2(u64 a, u64 b, u64 c) {
    u64 d; asm("fma.rn.f32x2 %0, %1, %2, %3;" : "=l"(d) : "l"(a), "l"(b), "l"(c)); return d;
}
__device__ __forceinline__ u64 mul2(u64 a, u64 b) {
    u64 d; asm("mul.rn.f32x2 %0, %1, %2;" : "=l"(d) : "l"(a), "l"(b)); return d;
}

__device__ __forceinline__ constexpr int tix(int i, int j) {  // i <= j
    return 8 * i - (i * (i - 1)) / 2 + (j - i);
}
__device__ __forceinline__ constexpr int symq(int i, int j) {
    return (i <= j) ? tix(i, j) : tix(j, i);
}

__global__ void __launch_bounds__(NTHR)
ns_kernel(const float* __restrict__ x, const float* __restrict__ w,
          float* __restrict__ out)
{
    __shared__ float s[MPB * SROW];
    const int tid = threadIdx.x;
    const long long base = (long long)blockIdx.x * MPB * 64;

    // ---- stage in: coalesced float4 gmem -> padded smem (8B-aligned float2) ----
    const float4* __restrict__ gin = (const float4*)(x + base);
#pragma unroll
    for (int v = 0; v < 32; v++) {
        int g4 = tid + NTHR * v;              // 2048 float4 per block
        float4 d = gin[g4];
        int m = g4 >> 4, e = (g4 & 15) << 2;
        float2* p = (float2*)&s[m * SROW + e];
        p[0] = make_float2(d.x, d.y);
        p[1] = make_float2(d.z, d.w);
    }
    __syncthreads();

    // coefficients: q(Abar) = sum_{k=0..7} g_k Abar^k,
    // g7=w6 ... g1=w0, g0=w7+1 (identity + outer +x folded in)
    const u64 C7 = pack2(w[6], w[6]);
    const u64 D6 = pack2(w[5], w[5]);
    u64 CS[6];
    CS[0] = pack2(w[4], w[4]);
    CS[1] = pack2(w[3], w[3]);
    CS[2] = pack2(w[2], w[2]);
    CS[3] = pack2(w[1], w[1]);
    CS[4] = pack2(w[0], w[0]);
    CS[5] = pack2(w[7] + 1.0f, w[7] + 1.0f);
    const u64 NEG1 = pack2(-1.0f, -1.0f);
    const u64 ONE2 = pack2(1.0f, 1.0f);

    float* __restrict__ sA = &s[tid * SROW];            // matrix A region
    float* __restrict__ sB = &s[(tid + NTHR) * SROW];   // matrix B region

    // ---- Gram accumulators: G = x^T x, outer-product over rows (pairs) ----
    u64 acc[36];
#pragma unroll
    for (int q = 0; q < 36; q++) acc[q] = 0ULL;

#pragma unroll
    for (int k = 0; k < 8; k++) {
        u64 xk[8];
#pragma unroll
        for (int q = 0; q < 4; q++) {
            u64 va = *(const u64*)&sA[k * 8 + 2 * q];
            u64 vb = *(const u64*)&sB[k * 8 + 2 * q];
            float a0, a1, b0, b1;
            unpack2(va, a0, a1);
            unpack2(vb, b0, b1);
            xk[2 * q]     = pack2(a0, b0);
            xk[2 * q + 1] = pack2(a1, b1);
        }
#pragma unroll
        for (int i = 0; i < 8; i++)
#pragma unroll
            for (int j = i; j < 8; j++)
                acc[tix(i, j)] = fma2(xk[i], xk[j], acc[tix(i, j)]);
    }

    // ---- Abar = I - G ----
    u64 Ab[36];
#pragma unroll
    for (int i = 0; i < 8; i++)
#pragma unroll
        for (int j = i; j < 8; j++)
            Ab[tix(i, j)] = fma2(acc[tix(i, j)], NEG1, (i == j) ? ONE2 : 0ULL);

    // ---- T = g7*Abar + g6*I ----
    u64 T[36];
#pragma unroll
    for (int i = 0; i < 8; i++)
#pragma unroll
        for (int j = i; j < 8; j++)
            T[tix(i, j)] = fma2(Ab[tix(i, j)], C7, (i == j) ? D6 : 0ULL);

    // ---- 6 Horner steps: T <- Abar*T + cs*I (symmetric triangular) ----
#pragma unroll
    for (int sIdx = 0; sIdx < 6; sIdx++) {
        u64 N[36];
#pragma unroll
        for (int i = 0; i < 8; i++) {
#pragma unroll
            for (int j = i; j < 8; j++) {
                u64 a = (i == j) ? CS[sIdx] : 0ULL;
#pragma unroll
                for (int m = 0; m < 8; m++)
                    a = fma2(Ab[symq(i, m)], T[symq(m, j)], a);
                N[tix(i, j)] = a;
            }
        }
#pragma unroll
        for (int q = 0; q < 36; q++) T[q] = N[q];
    }

    // ---- out = x @ T  (row-wise, in place in smem) ----
#pragma unroll
    for (int i = 0; i < 8; i++) {
        u64 xk[8];
#pragma unroll
        for (int q = 0; q < 4; q++) {
            u64 va = *(const u64*)&sA[i * 8 + 2 * q];
            u64 vb = *(const u64*)&sB[i * 8 + 2 * q];
            float a0, a1, b0, b1;
            unpack2(va, a0, a1);
            unpack2(vb, b0, b1);
            xk[2 * q]     = pack2(a0, b0);
            xk[2 * q + 1] = pack2(a1, b1);
        }
        u64 o[8];
#pragma unroll
        for (int j = 0; j < 8; j++) {
            u64 a = mul2(xk[0], T[symq(0, j)]);
#pragma unroll
            for (int k = 1; k < 8; k++)
                a = fma2(xk[k], T[symq(k, j)], a);
            o[j] = a;
        }
        // unpack lanes back to the two matrices and store as 8B pairs
#pragma unroll
        for (int q = 0; q < 4; q++) {
            float a0, b0, a1, b1;
            unpack2(o[2 * q],     a0, b0);
            unpack2(o[2 * q + 1], a1, b1);
            *(u64*)&sA[i * 8 + 2 * q] = pack2(a0, a1);
            *(u64*)&sB[i * 8 + 2 * q] = pack2(b0, b1);
        }
    }
    __syncthreads();

    // ---- stage out: padded smem -> coalesced float4 gmem ----
    float4* __restrict__ gout = (float4*)(out + base);
#pragma unroll
    for (int v = 0; v < 32; v++) {
        int g4 = tid + NTHR * v;
        int m = g4 >> 4, e = (g4 & 15) << 2;
        const float2* p = (const float2*)&s[m * SROW + e];
        float2 a = p[0], b = p[1];
        gout[g4] = make_float4(a.x, a.y, b.x, b.y);
    }
}

extern "C" void kernel_launch(void* const* d_in, const int* in_sizes, int n_in,
                              void* d_out, int out_size) {
    const float* x = (const float*)d_in[0];   // (2048,128,8,8) fp32
    const float* w = (const float*)d_in[1];   // (14,) fp32
    float* out = (float*)d_out;

    int nmat = in_sizes[0] / 64;              // 262144
    int grid = nmat / MPB;                    // 2048
    ns_kernel<<<grid, NTHR>>>(x, w, out);
}